// round 3
// baseline (speedup 1.0000x reference)
#include <cuda_runtime.h>
#include <math.h>
#include <stdint.h>

#define NA 8192
#define MBND 16
#define HID 256
#define NHEAD 8

// ---------------- scratch (device globals; no allocation allowed) ----------------
__device__ float g_qkv[NA * 768];
__device__ float g_o[NA * HID];
__device__ float g_x1[NA * HID];
__device__ float g_Ab[NA * HID];
__device__ float g_sc[NA * MBND * NHEAD];
__device__ float g_x2[NA * HID];
__device__ float g_hf[NA * 1024];

enum { EPI_BIAS = 0, EPI_BIAS_RELU = 1, EPI_RES_LN = 2, EPI_NB = 3 };

// ---------------------------------------------------------------------------
// Generic tiled SGEMM: C[M,N] = A[M,K] @ B[K,N] (+ fused epilogues)
// BM=64, BN=256, BK=8, 256 threads, 8x8 microtile (rows consecutive, cols
// strided by 32 so each warp owns 8 full rows of 256 cols -> warp-level LN).
// Requires M%64==0, N%256==0, K%8==0 (all shapes here satisfy this).
// ---------------------------------------------------------------------------
template <int EPI>
__global__ __launch_bounds__(256, 2)
void gemm_kernel(const float* __restrict__ A, const float* __restrict__ B,
                 const float* __restrict__ bias, float* __restrict__ C,
                 int M, int N, int K,
                 const float* __restrict__ res,
                 const float* __restrict__ lng, const float* __restrict__ lnb,
                 const float* __restrict__ Ab, const float* __restrict__ W2,
                 const float* __restrict__ b2, float* __restrict__ scores)
{
    __shared__ float As[2][8][64];
    __shared__ float Bs[2][8][256];

    const int tid = threadIdx.x;
    const int tr = tid >> 5;   // 0..7 (row group; warp id)
    const int tc = tid & 31;   // 0..31 (lane; col group)
    const int bm = blockIdx.y * 64;
    const int bn = blockIdx.x * 256;

    const int a_r = tid >> 2;         // 0..63
    const int a_c = (tid & 3) * 2;    // 0,2,4,6
    const int b_k = tid >> 5;         // 0..7

    float acc[8][8];
#pragma unroll
    for (int i = 0; i < 8; i++)
#pragma unroll
        for (int j = 0; j < 8; j++) acc[i][j] = 0.f;

    const int nk = K >> 3;

    // prologue: tile 0
    {
        float2 av = *(const float2*)(A + (size_t)(bm + a_r) * K + a_c);
        As[0][a_c][a_r] = av.x;
        As[0][a_c + 1][a_r] = av.y;
#pragma unroll
        for (int j = 0; j < 8; j++)
            Bs[0][b_k][tc + 32 * j] = B[(size_t)b_k * N + bn + tc + 32 * j];
    }
    __syncthreads();

    for (int t = 0; t < nk; t++) {
        const int cur = t & 1, nxt = cur ^ 1;
        float2 av;
        float rb[8];
        if (t + 1 < nk) {
            const int kk = (t + 1) << 3;
            av = *(const float2*)(A + (size_t)(bm + a_r) * K + kk + a_c);
#pragma unroll
            for (int j = 0; j < 8; j++)
                rb[j] = B[(size_t)(kk + b_k) * N + bn + tc + 32 * j];
        }
#pragma unroll
        for (int k = 0; k < 8; k++) {
            float ra[8], rB[8];
#pragma unroll
            for (int i = 0; i < 8; i++) ra[i] = As[cur][k][tr * 8 + i];
#pragma unroll
            for (int j = 0; j < 8; j++) rB[j] = Bs[cur][k][tc + 32 * j];
#pragma unroll
            for (int i = 0; i < 8; i++)
#pragma unroll
                for (int j = 0; j < 8; j++)
                    acc[i][j] = fmaf(ra[i], rB[j], acc[i][j]);
        }
        if (t + 1 < nk) {
            As[nxt][a_c][a_r] = av.x;
            As[nxt][a_c + 1][a_r] = av.y;
#pragma unroll
            for (int j = 0; j < 8; j++) Bs[nxt][b_k][tc + 32 * j] = rb[j];
        }
        __syncthreads();
    }

    // ------------------------- epilogues -------------------------
    if (EPI == EPI_BIAS || EPI == EPI_BIAS_RELU) {
#pragma unroll
        for (int i = 0; i < 8; i++) {
            const int row = bm + tr * 8 + i;
#pragma unroll
            for (int j = 0; j < 8; j++) {
                const int col = bn + tc + 32 * j;
                float v = acc[i][j] + bias[col];
                if (EPI == EPI_BIAS_RELU) v = fmaxf(v, 0.f);
                C[(size_t)row * N + col] = v;
            }
        }
    } else if (EPI == EPI_RES_LN) {
        // N == 256, bn == 0: warp (fixed tr) holds all 256 cols of its 8 rows
#pragma unroll
        for (int i = 0; i < 8; i++) {
            const int row = bm + tr * 8 + i;
            float v[8], s = 0.f, ss = 0.f;
#pragma unroll
            for (int j = 0; j < 8; j++) {
                const int col = tc + 32 * j;
                v[j] = acc[i][j] + bias[col] + res[(size_t)row * 256 + col];
                s += v[j];
                ss += v[j] * v[j];
            }
#pragma unroll
            for (int off = 16; off > 0; off >>= 1) {
                s += __shfl_xor_sync(0xffffffffu, s, off);
                ss += __shfl_xor_sync(0xffffffffu, ss, off);
            }
            const float mu = s * (1.f / 256.f);
            const float var = ss * (1.f / 256.f) - mu * mu;
            const float rstd = rsqrtf(var + 1e-5f);
#pragma unroll
            for (int j = 0; j < 8; j++) {
                const int col = tc + 32 * j;
                C[(size_t)row * 256 + col] = (v[j] - mu) * rstd * lng[col] + lnb[col];
            }
        }
    } else {  // EPI_NB: h = relu(acc + Ab[atom]); scores[row] = h @ W2 + b2
#pragma unroll
        for (int i = 0; i < 8; i++) {
            const int row = bm + tr * 8 + i;   // bond index
            const int atom = row >> 4;
            float sc[8];
#pragma unroll
            for (int hh = 0; hh < 8; hh++) sc[hh] = 0.f;
#pragma unroll
            for (int j = 0; j < 8; j++) {
                const int col = tc + 32 * j;
                float h = acc[i][j] + Ab[(size_t)atom * 256 + col];
                h = fmaxf(h, 0.f);
                const float4 w0 = *(const float4*)(W2 + col * 8);
                const float4 w1 = *(const float4*)(W2 + col * 8 + 4);
                sc[0] += h * w0.x; sc[1] += h * w0.y;
                sc[2] += h * w0.z; sc[3] += h * w0.w;
                sc[4] += h * w1.x; sc[5] += h * w1.y;
                sc[6] += h * w1.z; sc[7] += h * w1.w;
            }
#pragma unroll
            for (int off = 16; off > 0; off >>= 1)
#pragma unroll
                for (int hh = 0; hh < 8; hh++)
                    sc[hh] += __shfl_xor_sync(0xffffffffu, sc[hh], off);
            if (tc == 0) {
#pragma unroll
                for (int hh = 0; hh < 8; hh++)
                    scores[(size_t)row * 8 + hh] = sc[hh] + b2[hh];
            }
        }
    }
}

// ---------------------------------------------------------------------------
// Flash attention, fp32. grid = (128 q-blocks, 8 heads), 256 threads.
// Q/K/V tiles 64x32 in smem; S/P 64x64 via registers+smem; online softmax.
// qkv layout per row: [q(256) | k(256) | v(256)]
// ---------------------------------------------------------------------------
__global__ __launch_bounds__(256)
void attn_kernel(const float* __restrict__ qkv, float* __restrict__ o)
{
    const int head = blockIdx.y;
    const int qb = blockIdx.x;

    __shared__ float Qs[64][33];
    __shared__ float Ks[64][33];
    __shared__ float Vs[64][33];
    __shared__ float Ss[64][65];

    const int tid = threadIdx.x;
    const int lr = tid >> 2;           // 0..63
    const int ldd = (tid & 3) * 8;     // 0,8,16,24
    {
        const float* src = qkv + (size_t)(qb * 64 + lr) * 768 + head * 32 + ldd;
#pragma unroll
        for (int u = 0; u < 8; u++) Qs[lr][ldd + u] = src[u];
    }

    const int rg = tid >> 4;  // 0..15 (4 rows each)
    const int cg = tid & 15;  // 0..15 (4 key-cols each / 2 O-cols each)

    float m[4], l[4], O0[4], O1[4];
#pragma unroll
    for (int i = 0; i < 4; i++) { m[i] = -1e30f; l[i] = 0.f; O0[i] = 0.f; O1[i] = 0.f; }
    const float scale = 0.17677669529663687f;  // 1/sqrt(32)

    for (int kb = 0; kb < 128; kb++) {
        __syncthreads();
        {
            const float* kp = qkv + (size_t)(kb * 64 + lr) * 768 + 256 + head * 32 + ldd;
#pragma unroll
            for (int u = 0; u < 8; u++) Ks[lr][ldd + u] = kp[u];
#pragma unroll
            for (int u = 0; u < 8; u++) Vs[lr][ldd + u] = kp[256 + u];
        }
        __syncthreads();

        float s[4][4];
#pragma unroll
        for (int i = 0; i < 4; i++)
#pragma unroll
            for (int j = 0; j < 4; j++) s[i][j] = 0.f;
#pragma unroll 4
        for (int d = 0; d < 32; d++) {
            float qv[4], kv[4];
#pragma unroll
            for (int i = 0; i < 4; i++) qv[i] = Qs[rg * 4 + i][d];
#pragma unroll
            for (int j = 0; j < 4; j++) kv[j] = Ks[cg * 4 + j][d];
#pragma unroll
            for (int i = 0; i < 4; i++)
#pragma unroll
                for (int j = 0; j < 4; j++)
                    s[i][j] = fmaf(qv[i], kv[j], s[i][j]);
        }

#pragma unroll
        for (int i = 0; i < 4; i++) {
            float rmax = -1e30f;
#pragma unroll
            for (int j = 0; j < 4; j++) { s[i][j] *= scale; rmax = fmaxf(rmax, s[i][j]); }
#pragma unroll
            for (int off = 8; off > 0; off >>= 1)
                rmax = fmaxf(rmax, __shfl_xor_sync(0xffffffffu, rmax, off, 16));
            const float mnew = fmaxf(m[i], rmax);
            const float alpha = __expf(m[i] - mnew);
            float rsum = 0.f;
#pragma unroll
            for (int j = 0; j < 4; j++) {
                const float p = __expf(s[i][j] - mnew);
                Ss[rg * 4 + i][cg * 4 + j] = p;
                rsum += p;
            }
#pragma unroll
            for (int off = 8; off > 0; off >>= 1)
                rsum += __shfl_xor_sync(0xffffffffu, rsum, off, 16);
            l[i] = l[i] * alpha + rsum;
            m[i] = mnew;
            O0[i] *= alpha;
            O1[i] *= alpha;
        }
        __syncthreads();

#pragma unroll 8
        for (int k = 0; k < 64; k++) {
            const float v0 = Vs[k][cg * 2];
            const float v1 = Vs[k][cg * 2 + 1];
#pragma unroll
            for (int i = 0; i < 4; i++) {
                const float p = Ss[rg * 4 + i][k];
                O0[i] = fmaf(p, v0, O0[i]);
                O1[i] = fmaf(p, v1, O1[i]);
            }
        }
    }

#pragma unroll
    for (int i = 0; i < 4; i++) {
        const float inv = 1.f / l[i];
        const int row = qb * 64 + rg * 4 + i;
        float* dst = o + (size_t)row * 256 + head * 32 + cg * 2;
        dst[0] = O0[i] * inv;
        dst[1] = O1[i] * inv;
    }
}

// ---------------------------------------------------------------------------
// Bond softmax (per head, over 16 bonds) -> mean over heads -> weighted
// message sum -> x2 = x1 + message. One block (256 thr) per atom.
// ---------------------------------------------------------------------------
__global__ __launch_bounds__(256)
void msg_kernel(const float* __restrict__ neighbors,
                const float* __restrict__ edge,
                const float* __restrict__ scores,
                const float* __restrict__ x1,
                float* __restrict__ x2)
{
    const int n = blockIdx.x;
    const int tid = threadIdx.x;
    __shared__ float sc[16][8];
    __shared__ float w[16];

    if (tid < 128) sc[tid >> 3][tid & 7] = scores[(size_t)n * 128 + tid];
    __syncthreads();

    if (tid < 8) {
        const int h = tid;
        float mx = -1e30f;
#pragma unroll
        for (int mm = 0; mm < 16; mm++) mx = fmaxf(mx, sc[mm][h]);
        float e[16], s = 0.f;
#pragma unroll
        for (int mm = 0; mm < 16; mm++) { e[mm] = __expf(sc[mm][h] - mx); s += e[mm]; }
        const float invs = 1.f / s;
#pragma unroll
        for (int mm = 0; mm < 16; mm++) sc[mm][h] = e[mm] * invs;
    }
    __syncthreads();

    if (tid < 16) {
        float a = 0.f;
#pragma unroll
        for (int h = 0; h < 8; h++) a += sc[tid][h];
        w[tid] = a * 0.125f;
    }
    __syncthreads();

    const float* nb = neighbors + (size_t)n * MBND * 256 + tid;
    const float* ed = edge + (size_t)n * MBND * 256 + tid;
    float msg = 0.f;
#pragma unroll
    for (int mm = 0; mm < 16; mm++)
        msg += w[mm] * nb[mm * 256] * ed[mm * 256];
    x2[(size_t)n * 256 + tid] = x1[(size_t)n * 256 + tid] + msg;
}

// ---------------------------------------------------------------------------
extern "C" void kernel_launch(void* const* d_in, const int* in_sizes, int n_in,
                              void* d_out, int out_size)
{
    const float* x     = (const float*)d_in[0];
    const float* nbs   = (const float*)d_in[1];
    const float* edg   = (const float*)d_in[2];
    const float* in_w  = (const float*)d_in[3];
    const float* in_b  = (const float*)d_in[4];
    const float* out_w = (const float*)d_in[5];
    const float* out_b = (const float*)d_in[6];
    const float* ln1s  = (const float*)d_in[7];
    const float* ln1b  = (const float*)d_in[8];
    const float* na_w1 = (const float*)d_in[9];
    const float* na_b1 = (const float*)d_in[10];
    const float* na_w2 = (const float*)d_in[11];
    const float* na_b2 = (const float*)d_in[12];
    const float* ff_w1 = (const float*)d_in[13];
    const float* ff_b1 = (const float*)d_in[14];
    const float* ff_w2 = (const float*)d_in[15];
    const float* ff_b2 = (const float*)d_in[16];
    const float* ln2s  = (const float*)d_in[17];
    const float* ln2b  = (const float*)d_in[18];
    float* out = (float*)d_out;

    float *qkv, *o, *x1, *Ab, *sc, *x2, *hf;
    cudaGetSymbolAddress((void**)&qkv, g_qkv);
    cudaGetSymbolAddress((void**)&o,   g_o);
    cudaGetSymbolAddress((void**)&x1,  g_x1);
    cudaGetSymbolAddress((void**)&Ab,  g_Ab);
    cudaGetSymbolAddress((void**)&sc,  g_sc);
    cudaGetSymbolAddress((void**)&x2,  g_x2);
    cudaGetSymbolAddress((void**)&hf,  g_hf);

    const float* np = nullptr;
    dim3 thr(256);

    // 1) qkv = x @ in_proj_w + b        [8192,768]
    gemm_kernel<EPI_BIAS><<<dim3(3, 128), thr>>>(
        x, in_w, in_b, qkv, NA, 768, 256, np, np, np, np, np, np, nullptr);

    // 2) flash attention -> o           [8192,256]
    attn_kernel<<<dim3(128, 8), thr>>>(qkv, o);

    // 3) x1 = LN1(x + o @ out_proj_w + b)
    gemm_kernel<EPI_RES_LN><<<dim3(1, 128), thr>>>(
        o, out_w, out_b, x1, NA, 256, 256, x, ln1s, ln1b, np, np, np, nullptr);

    // 4) Ab = x1 @ na_w1[:256] + na_b1  (shared across an atom's 16 bonds)
    gemm_kernel<EPI_BIAS><<<dim3(1, 128), thr>>>(
        x1, na_w1, na_b1, Ab, NA, 256, 256, np, np, np, np, np, np, nullptr);

    // 5) scores[b,h] = relu(neighbors @ na_w1[256:] + Ab[atom]) @ na_w2 + b2
    gemm_kernel<EPI_NB><<<dim3(1, 2048), thr>>>(
        nbs, na_w1 + 256 * 256, np, nullptr, NA * MBND, 256, 256,
        np, np, np, Ab, na_w2, na_b2, sc);

    // 6) bond softmax + message; x2 = x1 + msg
    msg_kernel<<<NA, thr>>>(nbs, edg, sc, x1, x2);

    // 7) hf = relu(x2 @ ff_w1 + b)      [8192,1024]
    gemm_kernel<EPI_BIAS_RELU><<<dim3(4, 128), thr>>>(
        x2, ff_w1, ff_b1, hf, NA, 1024, 256, np, np, np, np, np, np, nullptr);

    // 8) out = LN2(x2 + hf @ ff_w2 + b)
    gemm_kernel<EPI_RES_LN><<<dim3(1, 128), thr>>>(
        hf, ff_w2, ff_b2, out, NA, 256, 1024, x2, ln2s, ln2b, np, np, np, nullptr);
}

// round 5
// speedup vs baseline: 2.1803x; 2.1803x over previous
#include <cuda_runtime.h>
#include <math.h>
#include <stdint.h>

#define NA 8192
#define MBND 16
#define HID 256
#define NHEAD 8

// ---------------- scratch (device globals; no allocation allowed) ----------------
__device__ float g_qkv[NA * 768];
__device__ float g_o[NA * HID];
__device__ float g_x1[NA * HID];
__device__ float g_Ab[NA * HID];
__device__ float g_sc[NA * MBND * NHEAD];
__device__ float g_x2[NA * HID];
__device__ float g_hf[NA * 1024];

enum { EPI_BIAS = 0, EPI_BIAS_RELU = 1, EPI_RES_LN = 2, EPI_NB = 3 };

// ---------------------------------------------------------------------------
// Generic tiled SGEMM (unchanged from round 0; attention was the bottleneck)
// ---------------------------------------------------------------------------
template <int EPI>
__global__ __launch_bounds__(256, 2)
void gemm_kernel(const float* __restrict__ A, const float* __restrict__ B,
                 const float* __restrict__ bias, float* __restrict__ C,
                 int M, int N, int K,
                 const float* __restrict__ res,
                 const float* __restrict__ lng, const float* __restrict__ lnb,
                 const float* __restrict__ Ab, const float* __restrict__ W2,
                 const float* __restrict__ b2, float* __restrict__ scores)
{
    __shared__ float As[2][8][64];
    __shared__ float Bs[2][8][256];

    const int tid = threadIdx.x;
    const int tr = tid >> 5;
    const int tc = tid & 31;
    const int bm = blockIdx.y * 64;
    const int bn = blockIdx.x * 256;

    const int a_r = tid >> 2;
    const int a_c = (tid & 3) * 2;
    const int b_k = tid >> 5;

    float acc[8][8];
#pragma unroll
    for (int i = 0; i < 8; i++)
#pragma unroll
        for (int j = 0; j < 8; j++) acc[i][j] = 0.f;

    const int nk = K >> 3;

    {
        float2 av = *(const float2*)(A + (size_t)(bm + a_r) * K + a_c);
        As[0][a_c][a_r] = av.x;
        As[0][a_c + 1][a_r] = av.y;
#pragma unroll
        for (int j = 0; j < 8; j++)
            Bs[0][b_k][tc + 32 * j] = B[(size_t)b_k * N + bn + tc + 32 * j];
    }
    __syncthreads();

    for (int t = 0; t < nk; t++) {
        const int cur = t & 1, nxt = cur ^ 1;
        float2 av;
        float rb[8];
        if (t + 1 < nk) {
            const int kk = (t + 1) << 3;
            av = *(const float2*)(A + (size_t)(bm + a_r) * K + kk + a_c);
#pragma unroll
            for (int j = 0; j < 8; j++)
                rb[j] = B[(size_t)(kk + b_k) * N + bn + tc + 32 * j];
        }
#pragma unroll
        for (int k = 0; k < 8; k++) {
            float ra[8], rB[8];
#pragma unroll
            for (int i = 0; i < 8; i++) ra[i] = As[cur][k][tr * 8 + i];
#pragma unroll
            for (int j = 0; j < 8; j++) rB[j] = Bs[cur][k][tc + 32 * j];
#pragma unroll
            for (int i = 0; i < 8; i++)
#pragma unroll
                for (int j = 0; j < 8; j++)
                    acc[i][j] = fmaf(ra[i], rB[j], acc[i][j]);
        }
        if (t + 1 < nk) {
            As[nxt][a_c][a_r] = av.x;
            As[nxt][a_c + 1][a_r] = av.y;
#pragma unroll
            for (int j = 0; j < 8; j++) Bs[nxt][b_k][tc + 32 * j] = rb[j];
        }
        __syncthreads();
    }

    if (EPI == EPI_BIAS || EPI == EPI_BIAS_RELU) {
#pragma unroll
        for (int i = 0; i < 8; i++) {
            const int row = bm + tr * 8 + i;
#pragma unroll
            for (int j = 0; j < 8; j++) {
                const int col = bn + tc + 32 * j;
                float v = acc[i][j] + bias[col];
                if (EPI == EPI_BIAS_RELU) v = fmaxf(v, 0.f);
                C[(size_t)row * N + col] = v;
            }
        }
    } else if (EPI == EPI_RES_LN) {
#pragma unroll
        for (int i = 0; i < 8; i++) {
            const int row = bm + tr * 8 + i;
            float v[8], s = 0.f, ss = 0.f;
#pragma unroll
            for (int j = 0; j < 8; j++) {
                const int col = tc + 32 * j;
                v[j] = acc[i][j] + bias[col] + res[(size_t)row * 256 + col];
                s += v[j];
                ss += v[j] * v[j];
            }
#pragma unroll
            for (int off = 16; off > 0; off >>= 1) {
                s += __shfl_xor_sync(0xffffffffu, s, off);
                ss += __shfl_xor_sync(0xffffffffu, ss, off);
            }
            const float mu = s * (1.f / 256.f);
            const float var = ss * (1.f / 256.f) - mu * mu;
            const float rstd = rsqrtf(var + 1e-5f);
#pragma unroll
            for (int j = 0; j < 8; j++) {
                const int col = tc + 32 * j;
                C[(size_t)row * 256 + col] = (v[j] - mu) * rstd * lng[col] + lnb[col];
            }
        }
    } else {  // EPI_NB
#pragma unroll
        for (int i = 0; i < 8; i++) {
            const int row = bm + tr * 8 + i;
            const int atom = row >> 4;
            float sc[8];
#pragma unroll
            for (int hh = 0; hh < 8; hh++) sc[hh] = 0.f;
#pragma unroll
            for (int j = 0; j < 8; j++) {
                const int col = tc + 32 * j;
                float h = acc[i][j] + Ab[(size_t)atom * 256 + col];
                h = fmaxf(h, 0.f);
                const float4 w0 = *(const float4*)(W2 + col * 8);
                const float4 w1 = *(const float4*)(W2 + col * 8 + 4);
                sc[0] += h * w0.x; sc[1] += h * w0.y;
                sc[2] += h * w0.z; sc[3] += h * w0.w;
                sc[4] += h * w1.x; sc[5] += h * w1.y;
                sc[6] += h * w1.z; sc[7] += h * w1.w;
            }
#pragma unroll
            for (int off = 16; off > 0; off >>= 1)
#pragma unroll
                for (int hh = 0; hh < 8; hh++)
                    sc[hh] += __shfl_xor_sync(0xffffffffu, sc[hh], off);
            if (tc == 0) {
#pragma unroll
                for (int hh = 0; hh < 8; hh++)
                    scores[(size_t)row * 8 + hh] = sc[hh] + b2[hh];
            }
        }
    }
}

// ---------------------------------------------------------------------------
// TF32 tensor-core flash attention.
// grid = (64 q-blocks, 8 heads), 256 threads = 8 warps; 16 q rows per warp.
// Q fragments live in registers (pre-scaled by 1/sqrt(32), tf32).
// K-tile = 64 keys. S via mma.m16n8k8 (4 k-steps x 8 n-tiles); online softmax
// on C fragments; P staged per-warp in smem; PV via mma (8 k-steps x 4 n-tiles).
// Smem pads (36 / 68) chosen so fragment LDS are bank-conflict-free.
// ---------------------------------------------------------------------------
__device__ __forceinline__ uint32_t cvt_tf32(float f) {
    uint32_t r;
    asm("cvt.rna.tf32.f32 %0, %1;" : "=r"(r) : "f"(f));
    return r;
}

__device__ __forceinline__ void mma_tf32(float* d, const uint32_t* a,
                                         uint32_t b0, uint32_t b1) {
    asm volatile(
        "mma.sync.aligned.m16n8k8.row.col.f32.tf32.tf32.f32 "
        "{%0,%1,%2,%3}, {%4,%5,%6,%7}, {%8,%9}, {%0,%1,%2,%3};"
        : "+f"(d[0]), "+f"(d[1]), "+f"(d[2]), "+f"(d[3])
        : "r"(a[0]), "r"(a[1]), "r"(a[2]), "r"(a[3]), "r"(b0), "r"(b1));
}

#define KPAD 36
#define PPAD 68

__global__ __launch_bounds__(256)
void attn_tc_kernel(const float* __restrict__ qkv, float* __restrict__ o)
{
    extern __shared__ float smem[];
    float* Ks = smem;                       // [64][36]
    float* Vs = smem + 64 * KPAD;           // [64][36]
    float* Ps = smem + 2 * 64 * KPAD;       // [8][16][68]

    const int head = blockIdx.y;
    const int qb   = blockIdx.x;
    const int tid  = threadIdx.x;
    const int wid  = tid >> 5;
    const int lane = tid & 31;
    const int g    = lane >> 2;    // 0..7
    const int c    = lane & 3;     // 0..3

    float* Pw = Ps + wid * 16 * PPAD;

    // ---- preload Q fragments (tf32, pre-scaled) ----
    const float scale = 0.17677669529663687f;  // 1/sqrt(32)
    const int qr0 = qb * 128 + wid * 16 + g;
    const float* qbase = qkv + (size_t)qr0 * 768 + head * 32;
    uint32_t qa[4][4];
#pragma unroll
    for (int kk = 0; kk < 4; kk++) {
        qa[kk][0] = cvt_tf32(qbase[kk * 8 + c] * scale);
        qa[kk][1] = cvt_tf32(qbase[8 * 768 + kk * 8 + c] * scale);
        qa[kk][2] = cvt_tf32(qbase[kk * 8 + 4 + c] * scale);
        qa[kk][3] = cvt_tf32(qbase[8 * 768 + kk * 8 + 4 + c] * scale);
    }

    float oacc[4][4];
#pragma unroll
    for (int nt = 0; nt < 4; nt++)
#pragma unroll
        for (int j = 0; j < 4; j++) oacc[nt][j] = 0.f;
    float mrow[2] = {-1e30f, -1e30f};
    float lrow[2] = {0.f, 0.f};

    const int key = tid >> 2;          // 0..63 (loader role)
    const int d4  = (tid & 3) * 8;     // 0,8,16,24

    for (int kb = 0; kb < 128; kb++) {
        __syncthreads();
        // ---- load K,V tile (tf32-converted) ----
        {
            const float* kp = qkv + (size_t)(kb * 64 + key) * 768 + 256 + head * 32 + d4;
            float4 k0 = *(const float4*)(kp);
            float4 k1 = *(const float4*)(kp + 4);
            float4 v0 = *(const float4*)(kp + 256);
            float4 v1 = *(const float4*)(kp + 260);
            float* kd = Ks + key * KPAD + d4;
            kd[0] = __uint_as_float(cvt_tf32(k0.x));
            kd[1] = __uint_as_float(cvt_tf32(k0.y));
            kd[2] = __uint_as_float(cvt_tf32(k0.z));
            kd[3] = __uint_as_float(cvt_tf32(k0.w));
            kd[4] = __uint_as_float(cvt_tf32(k1.x));
            kd[5] = __uint_as_float(cvt_tf32(k1.y));
            kd[6] = __uint_as_float(cvt_tf32(k1.z));
            kd[7] = __uint_as_float(cvt_tf32(k1.w));
            float* vd = Vs + key * KPAD + d4;
            vd[0] = __uint_as_float(cvt_tf32(v0.x));
            vd[1] = __uint_as_float(cvt_tf32(v0.y));
            vd[2] = __uint_as_float(cvt_tf32(v0.z));
            vd[3] = __uint_as_float(cvt_tf32(v0.w));
            vd[4] = __uint_as_float(cvt_tf32(v1.x));
            vd[5] = __uint_as_float(cvt_tf32(v1.y));
            vd[6] = __uint_as_float(cvt_tf32(v1.z));
            vd[7] = __uint_as_float(cvt_tf32(v1.w));
        }
        __syncthreads();

        // ---- S = Q K^T ----
        float sacc[8][4];
#pragma unroll
        for (int nt = 0; nt < 8; nt++)
#pragma unroll
            for (int j = 0; j < 4; j++) sacc[nt][j] = 0.f;

#pragma unroll
        for (int kk = 0; kk < 4; kk++) {
#pragma unroll
            for (int nt = 0; nt < 8; nt++) {
                const float* kp = Ks + (nt * 8 + g) * KPAD + kk * 8 + c;
                uint32_t b0 = __float_as_uint(kp[0]);
                uint32_t b1 = __float_as_uint(kp[4]);
                mma_tf32(sacc[nt], qa[kk], b0, b1);
            }
        }

        // ---- online softmax per row slot (rows g and g+8) ----
#pragma unroll
        for (int s = 0; s < 2; s++) {
            float mx = -1e30f;
#pragma unroll
            for (int nt = 0; nt < 8; nt++) {
                mx = fmaxf(mx, sacc[nt][2 * s]);
                mx = fmaxf(mx, sacc[nt][2 * s + 1]);
            }
            mx = fmaxf(mx, __shfl_xor_sync(0xffffffffu, mx, 1));
            mx = fmaxf(mx, __shfl_xor_sync(0xffffffffu, mx, 2));
            const float mnew = fmaxf(mrow[s], mx);
            const float alpha = __expf(mrow[s] - mnew);
            float lsum = 0.f;
#pragma unroll
            for (int nt = 0; nt < 8; nt++) {
                const float p0 = __expf(sacc[nt][2 * s] - mnew);
                const float p1 = __expf(sacc[nt][2 * s + 1] - mnew);
                lsum += p0 + p1;
                float2 pv;
                pv.x = __uint_as_float(cvt_tf32(p0));
                pv.y = __uint_as_float(cvt_tf32(p1));
                *(float2*)(Pw + (g + 8 * s) * PPAD + nt * 8 + 2 * c) = pv;
            }
            lsum += __shfl_xor_sync(0xffffffffu, lsum, 1);
            lsum += __shfl_xor_sync(0xffffffffu, lsum, 2);
            lrow[s] = lrow[s] * alpha + lsum;
            mrow[s] = mnew;
#pragma unroll
            for (int nt = 0; nt < 4; nt++) {
                oacc[nt][2 * s] *= alpha;
                oacc[nt][2 * s + 1] *= alpha;
            }
        }
        __syncwarp();

        // ---- O += P V ----
#pragma unroll
        for (int kk = 0; kk < 8; kk++) {
            uint32_t pa[4];
            pa[0] = __float_as_uint(Pw[g * PPAD + kk * 8 + c]);
            pa[1] = __float_as_uint(Pw[(g + 8) * PPAD + kk * 8 + c]);
            pa[2] = __float_as_uint(Pw[g * PPAD + kk * 8 + 4 + c]);
            pa[3] = __float_as_uint(Pw[(g + 8) * PPAD + kk * 8 + 4 + c]);
#pragma unroll
            for (int nt = 0; nt < 4; nt++) {
                uint32_t b0 = __float_as_uint(Vs[(kk * 8 + c) * KPAD + nt * 8 + g]);
                uint32_t b1 = __float_as_uint(Vs[(kk * 8 + 4 + c) * KPAD + nt * 8 + g]);
                mma_tf32(oacc[nt], pa, b0, b1);
            }
        }
    }

    // ---- epilogue: normalize and store ----
    const float inv0 = 1.f / lrow[0];
    const float inv1 = 1.f / lrow[1];
    const int orow = qb * 128 + wid * 16 + g;
#pragma unroll
    for (int nt = 0; nt < 4; nt++) {
        float2 v0, v1;
        v0.x = oacc[nt][0] * inv0;
        v0.y = oacc[nt][1] * inv0;
        v1.x = oacc[nt][2] * inv1;
        v1.y = oacc[nt][3] * inv1;
        *(float2*)(o + (size_t)orow * 256 + head * 32 + nt * 8 + 2 * c) = v0;
        *(float2*)(o + (size_t)(orow + 8) * 256 + head * 32 + nt * 8 + 2 * c) = v1;
    }
}

// ---------------------------------------------------------------------------
// Bond softmax + message (unchanged)
// ---------------------------------------------------------------------------
__global__ __launch_bounds__(256)
void msg_kernel(const float* __restrict__ neighbors,
                const float* __restrict__ edge,
                const float* __restrict__ scores,
                const float* __restrict__ x1,
                float* __restrict__ x2)
{
    const int n = blockIdx.x;
    const int tid = threadIdx.x;
    __shared__ float sc[16][8];
    __shared__ float w[16];

    if (tid < 128) sc[tid >> 3][tid & 7] = scores[(size_t)n * 128 + tid];
    __syncthreads();

    if (tid < 8) {
        const int h = tid;
        float mx = -1e30f;
#pragma unroll
        for (int mm = 0; mm < 16; mm++) mx = fmaxf(mx, sc[mm][h]);
        float e[16], s = 0.f;
#pragma unroll
        for (int mm = 0; mm < 16; mm++) { e[mm] = __expf(sc[mm][h] - mx); s += e[mm]; }
        const float invs = 1.f / s;
#pragma unroll
        for (int mm = 0; mm < 16; mm++) sc[mm][h] = e[mm] * invs;
    }
    __syncthreads();

    if (tid < 16) {
        float a = 0.f;
#pragma unroll
        for (int h = 0; h < 8; h++) a += sc[tid][h];
        w[tid] = a * 0.125f;
    }
    __syncthreads();

    const float* nb = neighbors + (size_t)n * MBND * 256 + tid;
    const float* ed = edge + (size_t)n * MBND * 256 + tid;
    float msg = 0.f;
#pragma unroll
    for (int mm = 0; mm < 16; mm++)
        msg += w[mm] * nb[mm * 256] * ed[mm * 256];
    x2[(size_t)n * 256 + tid] = x1[(size_t)n * 256 + tid] + msg;
}

// ---------------------------------------------------------------------------
extern "C" void kernel_launch(void* const* d_in, const int* in_sizes, int n_in,
                              void* d_out, int out_size)
{
    const float* x     = (const float*)d_in[0];
    const float* nbs   = (const float*)d_in[1];
    const float* edg   = (const float*)d_in[2];
    const float* in_w  = (const float*)d_in[3];
    const float* in_b  = (const float*)d_in[4];
    const float* out_w = (const float*)d_in[5];
    const float* out_b = (const float*)d_in[6];
    const float* ln1s  = (const float*)d_in[7];
    const float* ln1b  = (const float*)d_in[8];
    const float* na_w1 = (const float*)d_in[9];
    const float* na_b1 = (const float*)d_in[10];
    const float* na_w2 = (const float*)d_in[11];
    const float* na_b2 = (const float*)d_in[12];
    const float* ff_w1 = (const float*)d_in[13];
    const float* ff_b1 = (const float*)d_in[14];
    const float* ff_w2 = (const float*)d_in[15];
    const float* ff_b2 = (const float*)d_in[16];
    const float* ln2s  = (const float*)d_in[17];
    const float* ln2b  = (const float*)d_in[18];
    float* out = (float*)d_out;

    float *qkv, *o, *x1, *Ab, *sc, *x2, *hf;
    cudaGetSymbolAddress((void**)&qkv, g_qkv);
    cudaGetSymbolAddress((void**)&o,   g_o);
    cudaGetSymbolAddress((void**)&x1,  g_x1);
    cudaGetSymbolAddress((void**)&Ab,  g_Ab);
    cudaGetSymbolAddress((void**)&sc,  g_sc);
    cudaGetSymbolAddress((void**)&x2,  g_x2);
    cudaGetSymbolAddress((void**)&hf,  g_hf);

    const int attn_smem = (2 * 64 * KPAD + 8 * 16 * PPAD) * (int)sizeof(float);
    cudaFuncSetAttribute(attn_tc_kernel,
                         cudaFuncAttributeMaxDynamicSharedMemorySize, attn_smem);

    const float* np = nullptr;
    dim3 thr(256);

    // 1) qkv = x @ in_proj_w + b        [8192,768]
    gemm_kernel<EPI_BIAS><<<dim3(3, 128), thr>>>(
        x, in_w, in_b, qkv, NA, 768, 256, np, np, np, np, np, np, nullptr);

    // 2) tf32 flash attention -> o      [8192,256]
    attn_tc_kernel<<<dim3(64, 8), thr, attn_smem>>>(qkv, o);

    // 3) x1 = LN1(x + o @ out_proj_w + b)
    gemm_kernel<EPI_RES_LN><<<dim3(1, 128), thr>>>(
        o, out_w, out_b, x1, NA, 256, 256, x, ln1s, ln1b, np, np, np, nullptr);

    // 4) Ab = x1 @ na_w1[:256] + na_b1
    gemm_kernel<EPI_BIAS><<<dim3(1, 128), thr>>>(
        x1, na_w1, na_b1, Ab, NA, 256, 256, np, np, np, np, np, np, nullptr);

    // 5) scores = relu(neighbors @ na_w1[256:] + Ab[atom]) @ na_w2 + b2
    gemm_kernel<EPI_NB><<<dim3(1, 2048), thr>>>(
        nbs, na_w1 + 256 * 256, np, nullptr, NA * MBND, 256, 256,
        np, np, np, Ab, na_w2, na_b2, sc);

    // 6) bond softmax + message; x2 = x1 + msg
    msg_kernel<<<NA, thr>>>(nbs, edg, sc, x1, x2);

    // 7) hf = relu(x2 @ ff_w1 + b)      [8192,1024]
    gemm_kernel<EPI_BIAS_RELU><<<dim3(4, 128), thr>>>(
        x2, ff_w1, ff_b1, hf, NA, 1024, 256, np, np, np, np, np, np, nullptr);

    // 8) out = LN2(x2 + hf @ ff_w2 + b)
    gemm_kernel<EPI_RES_LN><<<dim3(1, 128), thr>>>(
        hf, ff_w2, ff_b2, out, NA, 256, 1024, x2, ln2s, ln2b, np, np, np, nullptr);
}

// round 6
// speedup vs baseline: 2.1805x; 1.0001x over previous
#include <cuda_runtime.h>
#include <math.h>
#include <stdint.h>

#define NA 8192
#define MBND 16
#define HID 256
#define NHEAD 8

// ---------------- scratch (device globals; no allocation allowed) ----------------
__device__ float g_qkv[NA * 768];
__device__ float g_o[NA * HID];
__device__ float g_x1[NA * HID];
__device__ float g_Ab[NA * HID];
__device__ float g_sc[NA * MBND * NHEAD];
__device__ float g_x2[NA * HID];
__device__ float g_hf[NA * 1024];

enum { EPI_BIAS = 0, EPI_BIAS_RELU = 1, EPI_RES_LN = 2, EPI_NB = 3 };

// ---------------------------------------------------------------------------
// Generic tiled SGEMM (unchanged from round 0; attention was the bottleneck)
// ---------------------------------------------------------------------------
template <int EPI>
__global__ __launch_bounds__(256, 2)
void gemm_kernel(const float* __restrict__ A, const float* __restrict__ B,
                 const float* __restrict__ bias, float* __restrict__ C,
                 int M, int N, int K,
                 const float* __restrict__ res,
                 const float* __restrict__ lng, const float* __restrict__ lnb,
                 const float* __restrict__ Ab, const float* __restrict__ W2,
                 const float* __restrict__ b2, float* __restrict__ scores)
{
    __shared__ float As[2][8][64];
    __shared__ float Bs[2][8][256];

    const int tid = threadIdx.x;
    const int tr = tid >> 5;
    const int tc = tid & 31;
    const int bm = blockIdx.y * 64;
    const int bn = blockIdx.x * 256;

    const int a_r = tid >> 2;
    const int a_c = (tid & 3) * 2;
    const int b_k = tid >> 5;

    float acc[8][8];
#pragma unroll
    for (int i = 0; i < 8; i++)
#pragma unroll
        for (int j = 0; j < 8; j++) acc[i][j] = 0.f;

    const int nk = K >> 3;

    {
        float2 av = *(const float2*)(A + (size_t)(bm + a_r) * K + a_c);
        As[0][a_c][a_r] = av.x;
        As[0][a_c + 1][a_r] = av.y;
#pragma unroll
        for (int j = 0; j < 8; j++)
            Bs[0][b_k][tc + 32 * j] = B[(size_t)b_k * N + bn + tc + 32 * j];
    }
    __syncthreads();

    for (int t = 0; t < nk; t++) {
        const int cur = t & 1, nxt = cur ^ 1;
        float2 av;
        float rb[8];
        if (t + 1 < nk) {
            const int kk = (t + 1) << 3;
            av = *(const float2*)(A + (size_t)(bm + a_r) * K + kk + a_c);
#pragma unroll
            for (int j = 0; j < 8; j++)
                rb[j] = B[(size_t)(kk + b_k) * N + bn + tc + 32 * j];
        }
#pragma unroll
        for (int k = 0; k < 8; k++) {
            float ra[8], rB[8];
#pragma unroll
            for (int i = 0; i < 8; i++) ra[i] = As[cur][k][tr * 8 + i];
#pragma unroll
            for (int j = 0; j < 8; j++) rB[j] = Bs[cur][k][tc + 32 * j];
#pragma unroll
            for (int i = 0; i < 8; i++)
#pragma unroll
                for (int j = 0; j < 8; j++)
                    acc[i][j] = fmaf(ra[i], rB[j], acc[i][j]);
        }
        if (t + 1 < nk) {
            As[nxt][a_c][a_r] = av.x;
            As[nxt][a_c + 1][a_r] = av.y;
#pragma unroll
            for (int j = 0; j < 8; j++) Bs[nxt][b_k][tc + 32 * j] = rb[j];
        }
        __syncthreads();
    }

    if (EPI == EPI_BIAS || EPI == EPI_BIAS_RELU) {
#pragma unroll
        for (int i = 0; i < 8; i++) {
            const int row = bm + tr * 8 + i;
#pragma unroll
            for (int j = 0; j < 8; j++) {
                const int col = bn + tc + 32 * j;
                float v = acc[i][j] + bias[col];
                if (EPI == EPI_BIAS_RELU) v = fmaxf(v, 0.f);
                C[(size_t)row * N + col] = v;
            }
        }
    } else if (EPI == EPI_RES_LN) {
#pragma unroll
        for (int i = 0; i < 8; i++) {
            const int row = bm + tr * 8 + i;
            float v[8], s = 0.f, ss = 0.f;
#pragma unroll
            for (int j = 0; j < 8; j++) {
                const int col = tc + 32 * j;
                v[j] = acc[i][j] + bias[col] + res[(size_t)row * 256 + col];
                s += v[j];
                ss += v[j] * v[j];
            }
#pragma unroll
            for (int off = 16; off > 0; off >>= 1) {
                s += __shfl_xor_sync(0xffffffffu, s, off);
                ss += __shfl_xor_sync(0xffffffffu, ss, off);
            }
            const float mu = s * (1.f / 256.f);
            const float var = ss * (1.f / 256.f) - mu * mu;
            const float rstd = rsqrtf(var + 1e-5f);
#pragma unroll
            for (int j = 0; j < 8; j++) {
                const int col = tc + 32 * j;
                C[(size_t)row * 256 + col] = (v[j] - mu) * rstd * lng[col] + lnb[col];
            }
        }
    } else {  // EPI_NB
#pragma unroll
        for (int i = 0; i < 8; i++) {
            const int row = bm + tr * 8 + i;
            const int atom = row >> 4;
            float sc[8];
#pragma unroll
            for (int hh = 0; hh < 8; hh++) sc[hh] = 0.f;
#pragma unroll
            for (int j = 0; j < 8; j++) {
                const int col = tc + 32 * j;
                float h = acc[i][j] + Ab[(size_t)atom * 256 + col];
                h = fmaxf(h, 0.f);
                const float4 w0 = *(const float4*)(W2 + col * 8);
                const float4 w1 = *(const float4*)(W2 + col * 8 + 4);
                sc[0] += h * w0.x; sc[1] += h * w0.y;
                sc[2] += h * w0.z; sc[3] += h * w0.w;
                sc[4] += h * w1.x; sc[5] += h * w1.y;
                sc[6] += h * w1.z; sc[7] += h * w1.w;
            }
#pragma unroll
            for (int off = 16; off > 0; off >>= 1)
#pragma unroll
                for (int hh = 0; hh < 8; hh++)
                    sc[hh] += __shfl_xor_sync(0xffffffffu, sc[hh], off);
            if (tc == 0) {
#pragma unroll
                for (int hh = 0; hh < 8; hh++)
                    scores[(size_t)row * 8 + hh] = sc[hh] + b2[hh];
            }
        }
    }
}

// ---------------------------------------------------------------------------
// TF32 tensor-core flash attention.
// grid = (64 q-blocks, 8 heads), 256 threads = 8 warps; 16 q rows per warp.
// Q fragments live in registers (pre-scaled by 1/sqrt(32), tf32).
// K-tile = 64 keys. S via mma.m16n8k8 (4 k-steps x 8 n-tiles); online softmax
// on C fragments; P staged per-warp in smem; PV via mma (8 k-steps x 4 n-tiles).
// Smem pads (36 / 68) chosen so fragment LDS are bank-conflict-free.
// ---------------------------------------------------------------------------
__device__ __forceinline__ uint32_t cvt_tf32(float f) {
    uint32_t r;
    asm("cvt.rna.tf32.f32 %0, %1;" : "=r"(r) : "f"(f));
    return r;
}

__device__ __forceinline__ void mma_tf32(float* d, const uint32_t* a,
                                         uint32_t b0, uint32_t b1) {
    asm volatile(
        "mma.sync.aligned.m16n8k8.row.col.f32.tf32.tf32.f32 "
        "{%0,%1,%2,%3}, {%4,%5,%6,%7}, {%8,%9}, {%0,%1,%2,%3};"
        : "+f"(d[0]), "+f"(d[1]), "+f"(d[2]), "+f"(d[3])
        : "r"(a[0]), "r"(a[1]), "r"(a[2]), "r"(a[3]), "r"(b0), "r"(b1));
}

#define KPAD 36
#define PPAD 68

__global__ __launch_bounds__(256)
void attn_tc_kernel(const float* __restrict__ qkv, float* __restrict__ o)
{
    extern __shared__ float smem[];
    float* Ks = smem;                       // [64][36]
    float* Vs = smem + 64 * KPAD;           // [64][36]
    float* Ps = smem + 2 * 64 * KPAD;       // [8][16][68]

    const int head = blockIdx.y;
    const int qb   = blockIdx.x;
    const int tid  = threadIdx.x;
    const int wid  = tid >> 5;
    const int lane = tid & 31;
    const int g    = lane >> 2;    // 0..7
    const int c    = lane & 3;     // 0..3

    float* Pw = Ps + wid * 16 * PPAD;

    // ---- preload Q fragments (tf32, pre-scaled) ----
    const float scale = 0.17677669529663687f;  // 1/sqrt(32)
    const int qr0 = qb * 128 + wid * 16 + g;
    const float* qbase = qkv + (size_t)qr0 * 768 + head * 32;
    uint32_t qa[4][4];
#pragma unroll
    for (int kk = 0; kk < 4; kk++) {
        qa[kk][0] = cvt_tf32(qbase[kk * 8 + c] * scale);
        qa[kk][1] = cvt_tf32(qbase[8 * 768 + kk * 8 + c] * scale);
        qa[kk][2] = cvt_tf32(qbase[kk * 8 + 4 + c] * scale);
        qa[kk][3] = cvt_tf32(qbase[8 * 768 + kk * 8 + 4 + c] * scale);
    }

    float oacc[4][4];
#pragma unroll
    for (int nt = 0; nt < 4; nt++)
#pragma unroll
        for (int j = 0; j < 4; j++) oacc[nt][j] = 0.f;
    float mrow[2] = {-1e30f, -1e30f};
    float lrow[2] = {0.f, 0.f};

    const int key = tid >> 2;          // 0..63 (loader role)
    const int d4  = (tid & 3) * 8;     // 0,8,16,24

    for (int kb = 0; kb < 128; kb++) {
        __syncthreads();
        // ---- load K,V tile (tf32-converted) ----
        {
            const float* kp = qkv + (size_t)(kb * 64 + key) * 768 + 256 + head * 32 + d4;
            float4 k0 = *(const float4*)(kp);
            float4 k1 = *(const float4*)(kp + 4);
            float4 v0 = *(const float4*)(kp + 256);
            float4 v1 = *(const float4*)(kp + 260);
            float* kd = Ks + key * KPAD + d4;
            kd[0] = __uint_as_float(cvt_tf32(k0.x));
            kd[1] = __uint_as_float(cvt_tf32(k0.y));
            kd[2] = __uint_as_float(cvt_tf32(k0.z));
            kd[3] = __uint_as_float(cvt_tf32(k0.w));
            kd[4] = __uint_as_float(cvt_tf32(k1.x));
            kd[5] = __uint_as_float(cvt_tf32(k1.y));
            kd[6] = __uint_as_float(cvt_tf32(k1.z));
            kd[7] = __uint_as_float(cvt_tf32(k1.w));
            float* vd = Vs + key * KPAD + d4;
            vd[0] = __uint_as_float(cvt_tf32(v0.x));
            vd[1] = __uint_as_float(cvt_tf32(v0.y));
            vd[2] = __uint_as_float(cvt_tf32(v0.z));
            vd[3] = __uint_as_float(cvt_tf32(v0.w));
            vd[4] = __uint_as_float(cvt_tf32(v1.x));
            vd[5] = __uint_as_float(cvt_tf32(v1.y));
            vd[6] = __uint_as_float(cvt_tf32(v1.z));
            vd[7] = __uint_as_float(cvt_tf32(v1.w));
        }
        __syncthreads();

        // ---- S = Q K^T ----
        float sacc[8][4];
#pragma unroll
        for (int nt = 0; nt < 8; nt++)
#pragma unroll
            for (int j = 0; j < 4; j++) sacc[nt][j] = 0.f;

#pragma unroll
        for (int kk = 0; kk < 4; kk++) {
#pragma unroll
            for (int nt = 0; nt < 8; nt++) {
                const float* kp = Ks + (nt * 8 + g) * KPAD + kk * 8 + c;
                uint32_t b0 = __float_as_uint(kp[0]);
                uint32_t b1 = __float_as_uint(kp[4]);
                mma_tf32(sacc[nt], qa[kk], b0, b1);
            }
        }

        // ---- online softmax per row slot (rows g and g+8) ----
#pragma unroll
        for (int s = 0; s < 2; s++) {
            float mx = -1e30f;
#pragma unroll
            for (int nt = 0; nt < 8; nt++) {
                mx = fmaxf(mx, sacc[nt][2 * s]);
                mx = fmaxf(mx, sacc[nt][2 * s + 1]);
            }
            mx = fmaxf(mx, __shfl_xor_sync(0xffffffffu, mx, 1));
            mx = fmaxf(mx, __shfl_xor_sync(0xffffffffu, mx, 2));
            const float mnew = fmaxf(mrow[s], mx);
            const float alpha = __expf(mrow[s] - mnew);
            float lsum = 0.f;
#pragma unroll
            for (int nt = 0; nt < 8; nt++) {
                const float p0 = __expf(sacc[nt][2 * s] - mnew);
                const float p1 = __expf(sacc[nt][2 * s + 1] - mnew);
                lsum += p0 + p1;
                float2 pv;
                pv.x = __uint_as_float(cvt_tf32(p0));
                pv.y = __uint_as_float(cvt_tf32(p1));
                *(float2*)(Pw + (g + 8 * s) * PPAD + nt * 8 + 2 * c) = pv;
            }
            lsum += __shfl_xor_sync(0xffffffffu, lsum, 1);
            lsum += __shfl_xor_sync(0xffffffffu, lsum, 2);
            lrow[s] = lrow[s] * alpha + lsum;
            mrow[s] = mnew;
#pragma unroll
            for (int nt = 0; nt < 4; nt++) {
                oacc[nt][2 * s] *= alpha;
                oacc[nt][2 * s + 1] *= alpha;
            }
        }
        __syncwarp();

        // ---- O += P V ----
#pragma unroll
        for (int kk = 0; kk < 8; kk++) {
            uint32_t pa[4];
            pa[0] = __float_as_uint(Pw[g * PPAD + kk * 8 + c]);
            pa[1] = __float_as_uint(Pw[(g + 8) * PPAD + kk * 8 + c]);
            pa[2] = __float_as_uint(Pw[g * PPAD + kk * 8 + 4 + c]);
            pa[3] = __float_as_uint(Pw[(g + 8) * PPAD + kk * 8 + 4 + c]);
#pragma unroll
            for (int nt = 0; nt < 4; nt++) {
                uint32_t b0 = __float_as_uint(Vs[(kk * 8 + c) * KPAD + nt * 8 + g]);
                uint32_t b1 = __float_as_uint(Vs[(kk * 8 + 4 + c) * KPAD + nt * 8 + g]);
                mma_tf32(oacc[nt], pa, b0, b1);
            }
        }
    }

    // ---- epilogue: normalize and store ----
    const float inv0 = 1.f / lrow[0];
    const float inv1 = 1.f / lrow[1];
    const int orow = qb * 128 + wid * 16 + g;
#pragma unroll
    for (int nt = 0; nt < 4; nt++) {
        float2 v0, v1;
        v0.x = oacc[nt][0] * inv0;
        v0.y = oacc[nt][1] * inv0;
        v1.x = oacc[nt][2] * inv1;
        v1.y = oacc[nt][3] * inv1;
        *(float2*)(o + (size_t)orow * 256 + head * 32 + nt * 8 + 2 * c) = v0;
        *(float2*)(o + (size_t)(orow + 8) * 256 + head * 32 + nt * 8 + 2 * c) = v1;
    }
}

// ---------------------------------------------------------------------------
// Bond softmax + message (unchanged)
// ---------------------------------------------------------------------------
__global__ __launch_bounds__(256)
void msg_kernel(const float* __restrict__ neighbors,
                const float* __restrict__ edge,
                const float* __restrict__ scores,
                const float* __restrict__ x1,
                float* __restrict__ x2)
{
    const int n = blockIdx.x;
    const int tid = threadIdx.x;
    __shared__ float sc[16][8];
    __shared__ float w[16];

    if (tid < 128) sc[tid >> 3][tid & 7] = scores[(size_t)n * 128 + tid];
    __syncthreads();

    if (tid < 8) {
        const int h = tid;
        float mx = -1e30f;
#pragma unroll
        for (int mm = 0; mm < 16; mm++) mx = fmaxf(mx, sc[mm][h]);
        float e[16], s = 0.f;
#pragma unroll
        for (int mm = 0; mm < 16; mm++) { e[mm] = __expf(sc[mm][h] - mx); s += e[mm]; }
        const float invs = 1.f / s;
#pragma unroll
        for (int mm = 0; mm < 16; mm++) sc[mm][h] = e[mm] * invs;
    }
    __syncthreads();

    if (tid < 16) {
        float a = 0.f;
#pragma unroll
        for (int h = 0; h < 8; h++) a += sc[tid][h];
        w[tid] = a * 0.125f;
    }
    __syncthreads();

    const float* nb = neighbors + (size_t)n * MBND * 256 + tid;
    const float* ed = edge + (size_t)n * MBND * 256 + tid;
    float msg = 0.f;
#pragma unroll
    for (int mm = 0; mm < 16; mm++)
        msg += w[mm] * nb[mm * 256] * ed[mm * 256];
    x2[(size_t)n * 256 + tid] = x1[(size_t)n * 256 + tid] + msg;
}

// ---------------------------------------------------------------------------
extern "C" void kernel_launch(void* const* d_in, const int* in_sizes, int n_in,
                              void* d_out, int out_size)
{
    const float* x     = (const float*)d_in[0];
    const float* nbs   = (const float*)d_in[1];
    const float* edg   = (const float*)d_in[2];
    const float* in_w  = (const float*)d_in[3];
    const float* in_b  = (const float*)d_in[4];
    const float* out_w = (const float*)d_in[5];
    const float* out_b = (const float*)d_in[6];
    const float* ln1s  = (const float*)d_in[7];
    const float* ln1b  = (const float*)d_in[8];
    const float* na_w1 = (const float*)d_in[9];
    const float* na_b1 = (const float*)d_in[10];
    const float* na_w2 = (const float*)d_in[11];
    const float* na_b2 = (const float*)d_in[12];
    const float* ff_w1 = (const float*)d_in[13];
    const float* ff_b1 = (const float*)d_in[14];
    const float* ff_w2 = (const float*)d_in[15];
    const float* ff_b2 = (const float*)d_in[16];
    const float* ln2s  = (const float*)d_in[17];
    const float* ln2b  = (const float*)d_in[18];
    float* out = (float*)d_out;

    float *qkv, *o, *x1, *Ab, *sc, *x2, *hf;
    cudaGetSymbolAddress((void**)&qkv, g_qkv);
    cudaGetSymbolAddress((void**)&o,   g_o);
    cudaGetSymbolAddress((void**)&x1,  g_x1);
    cudaGetSymbolAddress((void**)&Ab,  g_Ab);
    cudaGetSymbolAddress((void**)&sc,  g_sc);
    cudaGetSymbolAddress((void**)&x2,  g_x2);
    cudaGetSymbolAddress((void**)&hf,  g_hf);

    const int attn_smem = (2 * 64 * KPAD + 8 * 16 * PPAD) * (int)sizeof(float);
    cudaFuncSetAttribute(attn_tc_kernel,
                         cudaFuncAttributeMaxDynamicSharedMemorySize, attn_smem);

    const float* np = nullptr;
    dim3 thr(256);

    // 1) qkv = x @ in_proj_w + b        [8192,768]
    gemm_kernel<EPI_BIAS><<<dim3(3, 128), thr>>>(
        x, in_w, in_b, qkv, NA, 768, 256, np, np, np, np, np, np, nullptr);

    // 2) tf32 flash attention -> o      [8192,256]
    attn_tc_kernel<<<dim3(64, 8), thr, attn_smem>>>(qkv, o);

    // 3) x1 = LN1(x + o @ out_proj_w + b)
    gemm_kernel<EPI_RES_LN><<<dim3(1, 128), thr>>>(
        o, out_w, out_b, x1, NA, 256, 256, x, ln1s, ln1b, np, np, np, nullptr);

    // 4) Ab = x1 @ na_w1[:256] + na_b1
    gemm_kernel<EPI_BIAS><<<dim3(1, 128), thr>>>(
        x1, na_w1, na_b1, Ab, NA, 256, 256, np, np, np, np, np, np, nullptr);

    // 5) scores = relu(neighbors @ na_w1[256:] + Ab[atom]) @ na_w2 + b2
    gemm_kernel<EPI_NB><<<dim3(1, 2048), thr>>>(
        nbs, na_w1 + 256 * 256, np, nullptr, NA * MBND, 256, 256,
        np, np, np, Ab, na_w2, na_b2, sc);

    // 6) bond softmax + message; x2 = x1 + msg
    msg_kernel<<<NA, thr>>>(nbs, edg, sc, x1, x2);

    // 7) hf = relu(x2 @ ff_w1 + b)      [8192,1024]
    gemm_kernel<EPI_BIAS_RELU><<<dim3(4, 128), thr>>>(
        x2, ff_w1, ff_b1, hf, NA, 1024, 256, np, np, np, np, np, np, nullptr);

    // 8) out = LN2(x2 + hf @ ff_w2 + b)
    gemm_kernel<EPI_RES_LN><<<dim3(1, 128), thr>>>(
        hf, ff_w2, ff_b2, out, NA, 256, 1024, x2, ln2s, ln2b, np, np, np, nullptr);
}